// round 1
// baseline (speedup 1.0000x reference)
#include <cuda_runtime.h>
#include <cstdint>
#include <cstddef>

// Problem constants
#define KQ 131072
#define DQ 128
#define BQ 512
#define ZR 1024                    // 2*B rows of Z (z0 rows 0..511, z1 rows 512..1023)
#define INVT 14.2857142857142857f  // 1/0.07

// Scratch (device globals; no allocations allowed)
__device__ float g_invnorm[KQ];                 // per-column 1/||q_k||
__device__ float g_ZnT[DQ * ZR];                // normalized Z, TRANSPOSED: [d][row], stride ZR
__device__ float g_Pn[ZR * DQ];                 // normalized P rows: p0 rows 0..511, p1 rows 512..1023
__device__ unsigned long long g_best[ZR];       // packed (mapped_float<<32)|(~k) running argmax
__device__ float g_rowloss[ZR];                 // per-row -(logp_diag)

// ---------------------------------------------------------------------------
// f32x2 helpers (sm_100a packed fp32 — doubles FFMA throughput vs 3-reg FFMA)
// ---------------------------------------------------------------------------
__device__ __forceinline__ void ffma2(unsigned long long &acc, unsigned long long a, unsigned long long b) {
    asm("fma.rn.f32x2 %0, %1, %2, %0;" : "+l"(acc) : "l"(a), "l"(b));
}
__device__ __forceinline__ unsigned long long dup2(float x) {
    unsigned long long r;
    asm("mov.b64 %0, {%1, %1};" : "=l"(r) : "f"(x));
    return r;
}
__device__ __forceinline__ float2 unpack2(unsigned long long v) {
    float2 f;
    asm("mov.b64 {%0, %1}, %2;" : "=f"(f.x), "=f"(f.y) : "l"(v));
    return f;
}

// ---------------------------------------------------------------------------
// Kernel 1: normalize the four 512x128 row-blocks; also zero g_best.
// grid = 2048 blocks, 128 threads. Block b: group = b>>9 (0:p0,1:p1,2:z0,3:z1), row r = b&511.
// ---------------------------------------------------------------------------
__global__ void norm_rows_kernel(const float* __restrict__ p0, const float* __restrict__ p1,
                                 const float* __restrict__ z0, const float* __restrict__ z1) {
    int b = blockIdx.x;
    int t = threadIdx.x;
    int grp = b >> 9;
    int r = b & 511;
    const float* src = (grp == 0) ? p0 : (grp == 1) ? p1 : (grp == 2) ? z0 : z1;
    float v = src[r * DQ + t];

    __shared__ float red[128];
    red[t] = v * v;
    __syncthreads();
    for (int s = 64; s > 0; s >>= 1) {
        if (t < s) red[t] += red[t + s];
        __syncthreads();
    }
    float vn = v * rsqrtf(red[0]);

    if (grp == 0)       g_Pn[r * DQ + t] = vn;
    else if (grp == 1)  g_Pn[(512 + r) * DQ + t] = vn;
    else if (grp == 2)  g_ZnT[t * ZR + r] = vn;          // z0 -> Z rows 0..511 (transposed)
    else                g_ZnT[t * ZR + 512 + r] = vn;    // z1 -> Z rows 512..1023

    if (b < 8) g_best[b * 128 + t] = 0ull;               // reset argmax state every launch
}

// ---------------------------------------------------------------------------
// Kernel 2: per-column inverse norms of queue; also write new_queue_id region.
// grid = 512 blocks x 256 threads (one thread per column).
// ---------------------------------------------------------------------------
__global__ void col_norm_kernel(const float* __restrict__ queue, const int* __restrict__ queue_id,
                                const int* __restrict__ ids, float* __restrict__ out) {
    int k = blockIdx.x * 256 + threadIdx.x;
    float acc = 0.f;
#pragma unroll 8
    for (int d = 0; d < DQ; d++) {
        float q = queue[(size_t)d * KQ + k];
        acc += q * q;
    }
    g_invnorm[k] = rsqrtf(acc);
    out[1 + (size_t)DQ * KQ + k] = (float)((k < BQ) ? ids[k] : queue_id[k]);
}

// ---------------------------------------------------------------------------
// Kernel 3 (dominant): sim = Zn @ queue_n with fused argmax + new_queue write.
// Block tile: 128 rows (Z) x 256 cols (k). 256 threads, thread tile 8x16.
// Thread (ty,tx), tx=t&15, ty=t>>4:
//   rows: ty*4 + i*64 + r   (i=0..1, r=0..3)
//   cols: tx*4 + j*64 + c   (j=0..3, c=0..3)   -> conflict-free float4 LDS
// Inner product over d = 0..127 with f32x2 packed FMAs (64 per thread per d).
// ---------------------------------------------------------------------------
#define SIM_SMEM ((DQ * 128 + DQ * 256) * 4)   // A tile 64KB + B tile 128KB = 196608 B

__global__ void __launch_bounds__(256, 1)
sim_kernel(const float* __restrict__ queue, const int* __restrict__ queue_id,
           const int* __restrict__ ids, float* __restrict__ out) {
    extern __shared__ float smem[];
    float* As = smem;             // [d][m], stride 128
    float* Bs = smem + DQ * 128;  // [d][n], stride 256  (already normalized columns)
    __shared__ float s_inv[256];
    __shared__ int   s_qid[256];
    __shared__ int   s_ids[128];

    int t = threadIdx.x;
    int m0 = blockIdx.y * 128;
    int k0 = blockIdx.x * 256;

    if (t < 128) s_ids[t] = ids[(m0 + t) & 511];
    s_inv[t] = g_invnorm[k0 + t];
    s_qid[t] = queue_id[k0 + t];
    __syncthreads();

    // A tile: ZnT is already [d][row] -> direct coalesced copy
    for (int idx = t; idx < DQ * 32; idx += 256) {
        int d = idx >> 5, c = idx & 31;
        *(float4*)&As[d * 128 + c * 4] = *(const float4*)&g_ZnT[d * ZR + m0 + c * 4];
    }
    // B tile: load raw queue, scale by invnorm, stage to smem; m0==0 blocks also
    // write the normalized queue straight to the new_queue output region (fused).
    bool wr = (blockIdx.y == 0);
    for (int idx = t; idx < DQ * 64; idx += 256) {
        int d = idx >> 6, c = idx & 63;
        int k = k0 + c * 4;
        float4 q = *(const float4*)&queue[(size_t)d * KQ + k];
        float4 v;
        v.x = q.x * s_inv[c * 4];     v.y = q.y * s_inv[c * 4 + 1];
        v.z = q.z * s_inv[c * 4 + 2]; v.w = q.w * s_inv[c * 4 + 3];
        *(float4*)&Bs[d * 256 + c * 4] = v;
        if (wr) {
            size_t o = 1 + (size_t)d * KQ + k;   // +1 float => can't use float4 store
            out[o] = v.x; out[o + 1] = v.y; out[o + 2] = v.z; out[o + 3] = v.w;
        }
    }
    __syncthreads();

    int tx = t & 15, ty = t >> 4;
    unsigned long long acc[2][4][4][2];
#pragma unroll
    for (int i = 0; i < 2; i++)
#pragma unroll
        for (int r = 0; r < 4; r++)
#pragma unroll
            for (int j = 0; j < 4; j++) { acc[i][r][j][0] = 0ull; acc[i][r][j][1] = 0ull; }

    const float* Abase = As + ty * 4;
    const float* Bbase = Bs + tx * 4;

#pragma unroll 4
    for (int d = 0; d < DQ; d++) {
        float4 a0 = *(const float4*)(Abase + d * 128);
        float4 a1 = *(const float4*)(Abase + d * 128 + 64);
        ulonglong2 b0 = *(const ulonglong2*)(const void*)(Bbase + d * 256);
        ulonglong2 b1 = *(const ulonglong2*)(const void*)(Bbase + d * 256 + 64);
        ulonglong2 b2 = *(const ulonglong2*)(const void*)(Bbase + d * 256 + 128);
        ulonglong2 b3 = *(const ulonglong2*)(const void*)(Bbase + d * 256 + 192);
        float ar[2][4] = {{a0.x, a0.y, a0.z, a0.w}, {a1.x, a1.y, a1.z, a1.w}};
#pragma unroll
        for (int i = 0; i < 2; i++)
#pragma unroll
            for (int r = 0; r < 4; r++) {
                unsigned long long a2 = dup2(ar[i][r]);
                ffma2(acc[i][r][0][0], a2, b0.x); ffma2(acc[i][r][0][1], a2, b0.y);
                ffma2(acc[i][r][1][0], a2, b1.x); ffma2(acc[i][r][1][1], a2, b1.y);
                ffma2(acc[i][r][2][0], a2, b2.x); ffma2(acc[i][r][2][1], a2, b2.y);
                ffma2(acc[i][r][3][0], a2, b3.x); ffma2(acc[i][r][3][1], a2, b3.y);
            }
    }

    // Epilogue: mask own-id entries to -1, per-row argmax, merge globally.
#pragma unroll
    for (int i = 0; i < 2; i++)
#pragma unroll
        for (int r = 0; r < 4; r++) {
            int mrow = ty * 4 + i * 64 + r;
            int myid = s_ids[mrow];
            float best = -2.f;
            int bestn = 0;
#pragma unroll
            for (int j = 0; j < 4; j++)
#pragma unroll
                for (int p = 0; p < 2; p++) {
                    int n = tx * 4 + j * 64 + p * 2;
                    float2 v = unpack2(acc[i][r][j][p]);
                    float v0 = (s_qid[n] == myid) ? -1.f : v.x;
                    float v1 = (s_qid[n + 1] == myid) ? -1.f : v.y;
                    if (v0 > best) { best = v0; bestn = n; }
                    if (v1 > best) { best = v1; bestn = n + 1; }
                }
            // reduce across the 16 tx lanes that share this row
#pragma unroll
            for (int off = 1; off < 16; off <<= 1) {
                float ov = __shfl_xor_sync(0xFFFFFFFFu, best, off);
                int   on = __shfl_xor_sync(0xFFFFFFFFu, bestn, off);
                if (ov > best || (ov == best && on < bestn)) { best = ov; bestn = on; }
            }
            if (tx == 0) {
                unsigned u = __float_as_uint(best);
                u = (u & 0x80000000u) ? ~u : (u | 0x80000000u);  // monotone float->uint
                unsigned long long packed =
                    ((unsigned long long)u << 32) | (unsigned long long)(0xFFFFFFFFu - (unsigned)(k0 + bestn));
                int row = m0 + mrow;
                if (packed > g_best[row])   // cheap pre-filter; staleness only weakens filter
                    atomicMax(&g_best[row], packed);
            }
        }
}

// ---------------------------------------------------------------------------
// Kernel 4: overwrite new_queue columns 0..511 with z0^T (normalized).
// grid = 128 blocks (d), 512 threads (k).
// ---------------------------------------------------------------------------
__global__ void z0_write_kernel(float* __restrict__ out) {
    int d = blockIdx.x;
    int k = threadIdx.x;
    out[1 + (size_t)d * KQ + k] = g_ZnT[d * ZR + k];
}

// ---------------------------------------------------------------------------
// Kernel 5: per-row NT-Xent terms. grid = 1024 blocks (rows), 128 threads.
// Row i<512: logits0[i,j] = q_n[:,argmax_z1[i]] . p0[j] / T
// Row i>=512: logits1 with argmax_z0 and p1.
// ---------------------------------------------------------------------------
__global__ void loss_kernel(const float* __restrict__ queue) {
    int i = blockIdx.x;
    int t = threadIdx.x;
    __shared__ float nn[128];
    __shared__ float logits[512];
    __shared__ float red[128];

    int nnrow = (i < 512) ? (512 + i) : (i - 512);
    unsigned kidx = 0xFFFFFFFFu - (unsigned)(g_best[nnrow] & 0xFFFFFFFFull);
    nn[t] = queue[(size_t)t * KQ + kidx] * g_invnorm[kidx];
    __syncthreads();

    int pbase = (i < 512) ? 0 : 512;
    for (int jj = t; jj < 512; jj += 128) {
        const float* prow = &g_Pn[(size_t)(pbase + jj) * DQ];
        float dot = 0.f;
#pragma unroll
        for (int d = 0; d < 128; d += 4) {
            float4 p = *(const float4*)(prow + d);
            dot += nn[d] * p.x + nn[d + 1] * p.y + nn[d + 2] * p.z + nn[d + 3] * p.w;
        }
        logits[jj] = dot * INVT;
    }
    __syncthreads();

    float m = fmaxf(fmaxf(logits[t], logits[t + 128]), fmaxf(logits[t + 256], logits[t + 384]));
    red[t] = m;
    __syncthreads();
    for (int s = 64; s > 0; s >>= 1) { if (t < s) red[t] = fmaxf(red[t], red[t + s]); __syncthreads(); }
    float mx = red[0];
    __syncthreads();

    float sum = expf(logits[t] - mx) + expf(logits[t + 128] - mx) +
                expf(logits[t + 256] - mx) + expf(logits[t + 384] - mx);
    red[t] = sum;
    __syncthreads();
    for (int s = 64; s > 0; s >>= 1) { if (t < s) red[t] += red[t + s]; __syncthreads(); }

    if (t == 0) {
        float lse = mx + logf(red[0]);
        g_rowloss[i] = lse - logits[i & 511];   // -(logp_diag)
    }
}

// ---------------------------------------------------------------------------
// Kernel 6: deterministic final reduction; write loss and new_ptr.
// ---------------------------------------------------------------------------
__global__ void finalize_kernel(float* __restrict__ out, int out_size) {
    __shared__ float red[256];
    int t = threadIdx.x;
    red[t] = g_rowloss[t] + g_rowloss[t + 256] + g_rowloss[t + 512] + g_rowloss[t + 768];
    __syncthreads();
    for (int s = 128; s > 0; s >>= 1) { if (t < s) red[t] += red[t + s]; __syncthreads(); }
    if (t == 0) {
        out[0] = red[0] / 1024.f;       // ((loss0 + loss1)/2, each a mean over 512)
        out[out_size - 1] = 512.0f;     // new_ptr = (0 + B) % K
    }
}

// ---------------------------------------------------------------------------
extern "C" void kernel_launch(void* const* d_in, const int* in_sizes, int n_in,
                              void* d_out, int out_size) {
    const float* p0    = (const float*)d_in[0];
    const float* p1    = (const float*)d_in[1];
    const float* z0    = (const float*)d_in[2];
    const float* z1    = (const float*)d_in[3];
    const float* queue = (const float*)d_in[4];
    const int*   qid   = (const int*)d_in[5];
    const int*   ids   = (const int*)d_in[6];
    float* out = (float*)d_out;

    cudaFuncSetAttribute(sim_kernel, cudaFuncAttributeMaxDynamicSharedMemorySize, SIM_SMEM);

    norm_rows_kernel<<<2048, 128>>>(p0, p1, z0, z1);
    col_norm_kernel<<<512, 256>>>(queue, qid, ids, out);
    sim_kernel<<<dim3(KQ / 256, ZR / 128), 256, SIM_SMEM>>>(queue, qid, ids, out);
    z0_write_kernel<<<128, 512>>>(out);
    loss_kernel<<<1024, 128>>>(queue);
    finalize_kernel<<<1, 256>>>(out, out_size);
}